// round 9
// baseline (speedup 1.0000x reference)
#include <cuda_runtime.h>
#include <cstdint>
#include <cstddef>

#define B_ 256
#define L_ 512
#define D_ 768
#define C_ 19
#define CP 20
#define BL (B_*L_)

// Emission scratch, padded to 20 floats/row
__device__ float g_emis[(size_t)BL * CP];
// Score history: rows 0..512 per batch (row 0 = init, row t+1 = s after step t)
__device__ float g_hist[(size_t)B_ * (L_ + 1) * CP];

__device__ __forceinline__ unsigned long long pack2(float x){
    unsigned long long r;
    asm("mov.b64 %0, {%1, %1};" : "=l"(r) : "f"(x));
    return r;
}
__device__ __forceinline__ unsigned long long fma2(unsigned long long a,
                                                   unsigned long long b,
                                                   unsigned long long c){
    unsigned long long d;
    asm("fma.rn.f32x2 %0, %1, %2, %3;" : "=l"(d) : "l"(a), "l"(b), "l"(c));
    return d;
}

#define SMEM_A (D_ * 10 * 8)   // 61440 bytes: w2[d][p] packed class pairs

// ---------------------------------------------------------------------------
// Kernel A: emissions. R5's inner loop (R=4, LDS.128 weight loads, packed
// f32x2 FMA) repartitioned as 256 blocks x 128 threads: same 1024 total
// warps but spread over all 148 SMs (R5's grid=128 idled 20 SMs), and small
// enough blocks that 2-3 can co-reside where scheduled.
// ---------------------------------------------------------------------------
__global__ void __launch_bounds__(128) emis_kernel(const float* __restrict__ feats,
                                                   const float* __restrict__ W,
                                                   const float* __restrict__ bias){
    extern __shared__ unsigned long long w2[];   // [768*10]
    int tid = threadIdx.x;
    for (int i = tid; i < D_ * 10; i += 128){
        int d = i / 10, p = i % 10;
        float lo = W[(2*p) * D_ + d];
        float hi = (2*p + 1 < C_) ? W[(2*p + 1) * D_ + d] : 0.f;
        float2 t = make_float2(lo, hi);
        w2[i] = *reinterpret_cast<unsigned long long*>(&t);
    }
    __syncthreads();

    unsigned long long acc[4][10];
#pragma unroll
    for (int p = 0; p < 10; p++){
        float lo = bias[2*p];
        float hi = (2*p + 1 < C_) ? bias[2*p + 1] : 0.f;
        float2 t = make_float2(lo, hi);
        unsigned long long bv = *reinterpret_cast<unsigned long long*>(&t);
#pragma unroll
        for (int r = 0; r < 4; r++) acc[r][p] = bv;
    }

    size_t base = (size_t)blockIdx.x * 512 + tid;
    const float4* f0 = reinterpret_cast<const float4*>(feats + (base        ) * D_);
    const float4* f1 = reinterpret_cast<const float4*>(feats + (base + 128 ) * D_);
    const float4* f2 = reinterpret_cast<const float4*>(feats + (base + 256 ) * D_);
    const float4* f3 = reinterpret_cast<const float4*>(feats + (base + 384 ) * D_);

    for (int q = 0; q < D_ / 4; q++){
        float4 a = f0[q], b = f1[q], c = f2[q], dd4 = f3[q];
#pragma unroll
        for (int j = 0; j < 4; j++){
            unsigned long long p0 = pack2((&a.x)[j]);
            unsigned long long p1 = pack2((&b.x)[j]);
            unsigned long long p2 = pack2((&c.x)[j]);
            unsigned long long p3 = pack2((&dd4.x)[j]);
            int d = q * 4 + j;
#pragma unroll
            for (int pp = 0; pp < 5; pp++){
                ulonglong2 wv = *reinterpret_cast<const ulonglong2*>(&w2[d * 10 + pp * 2]);
                acc[0][2*pp]   = fma2(p0, wv.x, acc[0][2*pp]);
                acc[0][2*pp+1] = fma2(p0, wv.y, acc[0][2*pp+1]);
                acc[1][2*pp]   = fma2(p1, wv.x, acc[1][2*pp]);
                acc[1][2*pp+1] = fma2(p1, wv.y, acc[1][2*pp+1]);
                acc[2][2*pp]   = fma2(p2, wv.x, acc[2][2*pp]);
                acc[2][2*pp+1] = fma2(p2, wv.y, acc[2][2*pp+1]);
                acc[3][2*pp]   = fma2(p3, wv.x, acc[3][2*pp]);
                acc[3][2*pp+1] = fma2(p3, wv.y, acc[3][2*pp+1]);
            }
        }
    }

#pragma unroll
    for (int r = 0; r < 4; r++){
        unsigned long long* o =
            reinterpret_cast<unsigned long long*>(g_emis + (base + (size_t)r * 128) * CP);
#pragma unroll
        for (int p = 0; p < 10; p++) o[p] = acc[r][p];
    }
}

// ---------------------------------------------------------------------------
// Kernel B1: Viterbi forward (exact R5 version — best measured). 256 blocks
// x 32 threads, one warp per batch. SHFL gather, fma-form mask blend
// (bit-exact for m in {0,1}), history streamed to gmem for the bp kernel.
// ---------------------------------------------------------------------------
__global__ void __launch_bounds__(32) fwd_kernel(const float* __restrict__ masks,
                                                 const float* __restrict__ trans){
    __shared__ float m_sh[L_];
    int lane = threadIdx.x & 31;
    int b = blockIdx.x;
    bool active = lane < C_;
    int c = active ? lane : 0;

    float Trow[C_];
#pragma unroll
    for (int j = 0; j < C_; j++) Trow[j] = trans[c * C_ + j];

    const float* eb = g_emis + (size_t)b * L_ * CP;
    const float* mb = masks + (size_t)b * L_;
    float* ghb = g_hist + (size_t)b * (L_ + 1) * CP;

    for (int i = lane; i < L_; i += 32) m_sh[i] = mb[i];
    __syncwarp();

    float s = (lane == C_ - 2) ? 0.f : -10000.f;   // start_idx = C-2
    if (active) ghb[lane] = s;

    int ld_lane = active ? lane : 0;
    float e0 = eb[0 * CP + ld_lane];
    float e1 = eb[1 * CP + ld_lane];
    float e2 = eb[2 * CP + ld_lane];
    float e3 = eb[3 * CP + ld_lane];

#define VSTEP(T, EREG)                                                         \
    {                                                                          \
        float m = m_sh[T];                                                     \
        float om = 1.0f - m;                                                   \
        float inner = fmaf((EREG), m, s * om);   /* off critical path */       \
        float v[C_];                                                           \
        _Pragma("unroll")                                                      \
        for (int j = 0; j < C_; j++)                                           \
            v[j] = __shfl_sync(0xffffffffu, s, j) + Trow[j];                   \
        _Pragma("unroll")                                                      \
        for (int stp = 1; stp < C_; stp <<= 1){                                \
            _Pragma("unroll")                                                  \
            for (int j = 0; j + stp < C_; j += (stp << 1))                     \
                v[j] = fmaxf(v[j], v[j + stp]);                                \
        }                                                                      \
        s = fmaf(v[0], m, inner);                                              \
        if (active) ghb[((T) + 1) * CP + lane] = s;                            \
    }

    for (int t = 0; t < L_; t += 4){
        VSTEP(t, e0);     e0 = (t + 4 < L_) ? eb[(t + 4) * CP + ld_lane] : 0.f;
        VSTEP(t + 1, e1); e1 = (t + 5 < L_) ? eb[(t + 5) * CP + ld_lane] : 0.f;
        VSTEP(t + 2, e2); e2 = (t + 6 < L_) ? eb[(t + 6) * CP + ld_lane] : 0.f;
        VSTEP(t + 3, e3); e3 = (t + 7 < L_) ? eb[(t + 7) * CP + ld_lane] : 0.f;
    }
#undef VSTEP
}

// ---------------------------------------------------------------------------
// Kernel B2: backpointers + backtrace. One block per batch, one thread per
// timestep recomputes all 19 backpointers from the score history; thread 0
// backtraces from shared; coalesced tag writeback.
// ---------------------------------------------------------------------------
__global__ void __launch_bounds__(512) bp_kernel(const float* __restrict__ masks,
                                                 const float* __restrict__ trans,
                                                 float* __restrict__ out){
    __shared__ float T_sh[C_][CP];
    __shared__ float m2[L_];
    __shared__ signed char bp_sh[L_][CP];   // col 19 reused for tags
    int tid = threadIdx.x;
    int b = blockIdx.x;

    for (int i = tid; i < C_ * CP; i += 512){
        int cc = i / CP, j = i % CP;
        T_sh[cc][j] = (j < C_) ? trans[cc * C_ + j] : 0.f;
    }
    if (tid < L_) m2[tid] = masks[(size_t)b * L_ + tid];
    __syncthreads();

    {
        int t = tid;   // 0..511
        const float* h = g_hist + ((size_t)b * (L_ + 1) + t) * CP;
        float4 h0 = *reinterpret_cast<const float4*>(h + 0);
        float4 h1 = *reinterpret_cast<const float4*>(h + 4);
        float4 h2 = *reinterpret_cast<const float4*>(h + 8);
        float4 h3 = *reinterpret_cast<const float4*>(h + 12);
        float4 h4 = *reinterpret_cast<const float4*>(h + 16);
        float hv[C_];
        hv[0]=h0.x; hv[1]=h0.y; hv[2]=h0.z; hv[3]=h0.w;
        hv[4]=h1.x; hv[5]=h1.y; hv[6]=h1.z; hv[7]=h1.w;
        hv[8]=h2.x; hv[9]=h2.y; hv[10]=h2.z; hv[11]=h2.w;
        hv[12]=h3.x; hv[13]=h3.y; hv[14]=h3.z; hv[15]=h3.w;
        hv[16]=h4.x; hv[17]=h4.y; hv[18]=h4.z;

#pragma unroll
        for (int cc = 0; cc < C_; cc++){
            const float* tr = &T_sh[cc][0];
            float best = hv[0] + tr[0];
            int idx = 0;
#pragma unroll
            for (int j = 1; j < C_; j++){
                float val = hv[j] + tr[j];
                bool gt = val > best;          // strict > : leftmost wins ties
                best = gt ? val : best;
                idx  = gt ? j : idx;
            }
            bp_sh[t][cc] = (signed char)idx;
        }
    }

    // final score + start tag (warp 0)
    float fv = -3.4e38f; int fi = 999;
    if (tid < 32){
        int lane = tid;
        bool active = lane < C_;
        if (active)
            fv = g_hist[((size_t)b * (L_ + 1) + L_) * CP + lane]
               + trans[(C_ - 1) * C_ + lane];
        if (active) fi = lane;
#pragma unroll
        for (int off = 16; off > 0; off >>= 1){
            float ov = __shfl_down_sync(0xffffffffu, fv, off);
            int oi = __shfl_down_sync(0xffffffffu, fi, off);
            if (ov > fv || (ov == fv && oi < fi)){ fv = ov; fi = oi; }
        }
    }
    __syncthreads();

    if (tid == 0){
        out[b] = fv;
        int cur = fi;
        for (int t = L_ - 1; t >= 0; t--){
            bool valid = m2[t] > 0.f;
            bp_sh[t][C_] = valid ? (signed char)cur : (signed char)(-1);
            if (valid) cur = bp_sh[t][cur];
        }
    }
    __syncthreads();

    float* po = out + B_ + (size_t)b * L_;
    po[tid] = (float)bp_sh[tid][C_];
}

// ---------------------------------------------------------------------------
extern "C" void kernel_launch(void* const* d_in, const int* in_sizes, int n_in,
                              void* d_out, int out_size){
    const float* feats = (const float*)d_in[0];
    const float* masks = (const float*)d_in[1];
    const float* W     = (const float*)d_in[2];
    const float* bias  = (const float*)d_in[3];
    const float* trans = (const float*)d_in[4];
    float* out = (float*)d_out;

    cudaFuncSetAttribute(emis_kernel, cudaFuncAttributeMaxDynamicSharedMemorySize, SMEM_A);
    emis_kernel<<<256, 128, SMEM_A>>>(feats, W, bias);
    fwd_kernel<<<B_, 32>>>(masks, trans);
    bp_kernel<<<B_, 512>>>(masks, trans, out);
}

// round 10
// speedup vs baseline: 1.0665x; 1.0665x over previous
#include <cuda_runtime.h>
#include <cstdint>
#include <cstddef>

#define B_ 256
#define L_ 512
#define D_ 768
#define C_ 19
#define CP 20
#define BL (B_*L_)

#define QS 4                      // k-columns (float4 units) per stage
#define NSTAGE 48                 // 192 float4-cols / QS
#define ROWPAD 5                  // float4 slots per row (4 data + 1 pad)
#define STAGE_BYTES (512 * ROWPAD * 16)   // 40960
#define W_BYTES (D_ * 10 * 8)             // 61440
#define SMEM_TOT (W_BYTES + 3 * STAGE_BYTES)  // 184320

// Emission scratch, padded to 20 floats/row
__device__ float g_emis[(size_t)BL * CP];
// Score history: rows 0..512 per batch
__device__ float g_hist[(size_t)B_ * (L_ + 1) * CP];

__device__ __forceinline__ unsigned long long pack2(float x){
    unsigned long long r;
    asm("mov.b64 %0, {%1, %1};" : "=l"(r) : "f"(x));
    return r;
}
__device__ __forceinline__ unsigned long long fma2(unsigned long long a,
                                                   unsigned long long b,
                                                   unsigned long long c){
    unsigned long long d;
    asm("fma.rn.f32x2 %0, %1, %2, %3;" : "=l"(d) : "l"(a), "l"(b), "l"(c));
    return d;
}
__device__ __forceinline__ uint32_t smem_u32(const void* p){
    uint32_t a;
    asm("{ .reg .u64 t; cvta.to.shared.u64 t, %1; cvt.u32.u64 %0, t; }"
        : "=r"(a) : "l"(p));
    return a;
}
__device__ __forceinline__ void cp16(uint32_t dst, const void* src){
    asm volatile("cp.async.cg.shared.global [%0], [%1], 16;"
                 :: "r"(dst), "l"(src));
}

// ---------------------------------------------------------------------------
// Kernel A: emissions with cp.async feature staging. 256 blocks x 256 thr,
// 2 rows/thread. Triple-buffered stages of 4 float4-columns x 512 rows
// (40KB each); 2 stages in flight => ~80KB/SM outstanding (vs ~16KB with
// register prefetch — the kernel was DRAM-latency-bound). Copies coalesced
// (4 lanes x 64B per row); consumption padded to 80B/row. FFMA2 compute.
// ---------------------------------------------------------------------------
__global__ void __launch_bounds__(256) emis_kernel(const float* __restrict__ feats,
                                                   const float* __restrict__ W,
                                                   const float* __restrict__ bias){
    extern __shared__ char smem_raw[];
    unsigned long long* w2 = reinterpret_cast<unsigned long long*>(smem_raw);
    char* fbase = smem_raw + W_BYTES;
    uint32_t fb_u32 = smem_u32(fbase);
    int tid = threadIdx.x;

    // stage weights: w2[d*10 + p] = (W[2p][d], W[2p+1][d])
    for (int i = tid; i < D_ * 10; i += 256){
        int d = i / 10, p = i % 10;
        float lo = W[(2*p) * D_ + d];
        float hi = (2*p + 1 < C_) ? W[(2*p + 1) * D_ + d] : 0.f;
        float2 t = make_float2(lo, hi);
        w2[i] = *reinterpret_cast<unsigned long long*>(&t);
    }

    const float* gbase = feats + (size_t)blockIdx.x * 512 * D_;

#define ISSUE_STAGE(S)                                                         \
    {                                                                          \
        int buf = (S) % 3;                                                     \
        uint32_t bdst = fb_u32 + buf * STAGE_BYTES;                            \
        _Pragma("unroll")                                                      \
        for (int k = 0; k < 8; k++){                                           \
            int i = tid + k * 256;                                             \
            int q = i & 3, row = i >> 2;                                       \
            const float* src = gbase + (size_t)row * D_ + ((S) * QS + q) * 4;  \
            cp16(bdst + (row * ROWPAD + q) * 16, src);                         \
        }                                                                      \
        asm volatile("cp.async.commit_group;" ::: "memory");                   \
    }

    ISSUE_STAGE(0);
    ISSUE_STAGE(1);
    __syncthreads();   // weights visible; copies in flight

    unsigned long long accA[10], accB[10];
#pragma unroll
    for (int p = 0; p < 10; p++){
        float lo = bias[2*p];
        float hi = (2*p + 1 < C_) ? bias[2*p + 1] : 0.f;
        float2 t = make_float2(lo, hi);
        accA[p] = *reinterpret_cast<unsigned long long*>(&t);
        accB[p] = accA[p];
    }

    for (int s = 0; s < NSTAGE; s++){
        int buf = s % 3;
        asm volatile("cp.async.wait_group 1;" ::: "memory");  // stage s done
        __syncthreads();   // all threads' copies visible; buf (s+2)%3 free
        if (s + 2 < NSTAGE) ISSUE_STAGE(s + 2);

        const char* bsrc = fbase + buf * STAGE_BYTES;
#pragma unroll
        for (int q = 0; q < QS; q++){
            float4 a = *reinterpret_cast<const float4*>(
                bsrc + ((tid      ) * ROWPAD + q) * 16);
            float4 b = *reinterpret_cast<const float4*>(
                bsrc + ((tid + 256) * ROWPAD + q) * 16);
#pragma unroll
            for (int j = 0; j < 4; j++){
                unsigned long long pa = pack2((&a.x)[j]);
                unsigned long long pb = pack2((&b.x)[j]);
                int d = (s * QS + q) * 4 + j;
#pragma unroll
                for (int pp = 0; pp < 5; pp++){
                    ulonglong2 wv =
                        *reinterpret_cast<const ulonglong2*>(&w2[d * 10 + pp * 2]);
                    accA[2*pp]   = fma2(pa, wv.x, accA[2*pp]);
                    accA[2*pp+1] = fma2(pa, wv.y, accA[2*pp+1]);
                    accB[2*pp]   = fma2(pb, wv.x, accB[2*pp]);
                    accB[2*pp+1] = fma2(pb, wv.y, accB[2*pp+1]);
                }
            }
        }
    }
#undef ISSUE_STAGE

    size_t rowA = (size_t)blockIdx.x * 512 + tid;
    size_t rowB = rowA + 256;
    unsigned long long* oA = reinterpret_cast<unsigned long long*>(g_emis + rowA * CP);
    unsigned long long* oB = reinterpret_cast<unsigned long long*>(g_emis + rowB * CP);
#pragma unroll
    for (int p = 0; p < 10; p++){ oA[p] = accA[p]; oB[p] = accB[p]; }
}

// ---------------------------------------------------------------------------
// Kernel B1: Viterbi forward (exact R5 version). 256 blocks x 32 threads,
// one warp per batch. SHFL gather, fma-form mask blend (bit-exact for
// m in {0,1}), history streamed to gmem for the bp kernel.
// ---------------------------------------------------------------------------
__global__ void __launch_bounds__(32) fwd_kernel(const float* __restrict__ masks,
                                                 const float* __restrict__ trans){
    __shared__ float m_sh[L_];
    int lane = threadIdx.x & 31;
    int b = blockIdx.x;
    bool active = lane < C_;
    int c = active ? lane : 0;

    float Trow[C_];
#pragma unroll
    for (int j = 0; j < C_; j++) Trow[j] = trans[c * C_ + j];

    const float* eb = g_emis + (size_t)b * L_ * CP;
    const float* mb = masks + (size_t)b * L_;
    float* ghb = g_hist + (size_t)b * (L_ + 1) * CP;

    for (int i = lane; i < L_; i += 32) m_sh[i] = mb[i];
    __syncwarp();

    float s = (lane == C_ - 2) ? 0.f : -10000.f;   // start_idx = C-2
    if (active) ghb[lane] = s;

    int ld_lane = active ? lane : 0;
    float e0 = eb[0 * CP + ld_lane];
    float e1 = eb[1 * CP + ld_lane];
    float e2 = eb[2 * CP + ld_lane];
    float e3 = eb[3 * CP + ld_lane];

#define VSTEP(T, EREG)                                                         \
    {                                                                          \
        float m = m_sh[T];                                                     \
        float om = 1.0f - m;                                                   \
        float inner = fmaf((EREG), m, s * om);   /* off critical path */       \
        float v[C_];                                                           \
        _Pragma("unroll")                                                      \
        for (int j = 0; j < C_; j++)                                           \
            v[j] = __shfl_sync(0xffffffffu, s, j) + Trow[j];                   \
        _Pragma("unroll")                                                      \
        for (int stp = 1; stp < C_; stp <<= 1){                                \
            _Pragma("unroll")                                                  \
            for (int j = 0; j + stp < C_; j += (stp << 1))                     \
                v[j] = fmaxf(v[j], v[j + stp]);                                \
        }                                                                      \
        s = fmaf(v[0], m, inner);                                              \
        if (active) ghb[((T) + 1) * CP + lane] = s;                            \
    }

    for (int t = 0; t < L_; t += 4){
        VSTEP(t, e0);     e0 = (t + 4 < L_) ? eb[(t + 4) * CP + ld_lane] : 0.f;
        VSTEP(t + 1, e1); e1 = (t + 5 < L_) ? eb[(t + 5) * CP + ld_lane] : 0.f;
        VSTEP(t + 2, e2); e2 = (t + 6 < L_) ? eb[(t + 6) * CP + ld_lane] : 0.f;
        VSTEP(t + 3, e3); e3 = (t + 7 < L_) ? eb[(t + 7) * CP + ld_lane] : 0.f;
    }
#undef VSTEP
}

// ---------------------------------------------------------------------------
// Kernel B2: backpointers + backtrace (unchanged).
// ---------------------------------------------------------------------------
__global__ void __launch_bounds__(512) bp_kernel(const float* __restrict__ masks,
                                                 const float* __restrict__ trans,
                                                 float* __restrict__ out){
    __shared__ float T_sh[C_][CP];
    __shared__ float m2[L_];
    __shared__ signed char bp_sh[L_][CP];   // col 19 reused for tags
    int tid = threadIdx.x;
    int b = blockIdx.x;

    for (int i = tid; i < C_ * CP; i += 512){
        int cc = i / CP, j = i % CP;
        T_sh[cc][j] = (j < C_) ? trans[cc * C_ + j] : 0.f;
    }
    if (tid < L_) m2[tid] = masks[(size_t)b * L_ + tid];
    __syncthreads();

    {
        int t = tid;   // 0..511
        const float* h = g_hist + ((size_t)b * (L_ + 1) + t) * CP;
        float4 h0 = *reinterpret_cast<const float4*>(h + 0);
        float4 h1 = *reinterpret_cast<const float4*>(h + 4);
        float4 h2 = *reinterpret_cast<const float4*>(h + 8);
        float4 h3 = *reinterpret_cast<const float4*>(h + 12);
        float4 h4 = *reinterpret_cast<const float4*>(h + 16);
        float hv[C_];
        hv[0]=h0.x; hv[1]=h0.y; hv[2]=h0.z; hv[3]=h0.w;
        hv[4]=h1.x; hv[5]=h1.y; hv[6]=h1.z; hv[7]=h1.w;
        hv[8]=h2.x; hv[9]=h2.y; hv[10]=h2.z; hv[11]=h2.w;
        hv[12]=h3.x; hv[13]=h3.y; hv[14]=h3.z; hv[15]=h3.w;
        hv[16]=h4.x; hv[17]=h4.y; hv[18]=h4.z;

#pragma unroll
        for (int cc = 0; cc < C_; cc++){
            const float* tr = &T_sh[cc][0];
            float best = hv[0] + tr[0];
            int idx = 0;
#pragma unroll
            for (int j = 1; j < C_; j++){
                float val = hv[j] + tr[j];
                bool gt = val > best;          // strict > : leftmost wins ties
                best = gt ? val : best;
                idx  = gt ? j : idx;
            }
            bp_sh[t][cc] = (signed char)idx;
        }
    }

    // final score + start tag (warp 0)
    float fv = -3.4e38f; int fi = 999;
    if (tid < 32){
        int lane = tid;
        bool active = lane < C_;
        if (active)
            fv = g_hist[((size_t)b * (L_ + 1) + L_) * CP + lane]
               + trans[(C_ - 1) * C_ + lane];
        if (active) fi = lane;
#pragma unroll
        for (int off = 16; off > 0; off >>= 1){
            float ov = __shfl_down_sync(0xffffffffu, fv, off);
            int oi = __shfl_down_sync(0xffffffffu, fi, off);
            if (ov > fv || (ov == fv && oi < fi)){ fv = ov; fi = oi; }
        }
    }
    __syncthreads();

    if (tid == 0){
        out[b] = fv;
        int cur = fi;
        for (int t = L_ - 1; t >= 0; t--){
            bool valid = m2[t] > 0.f;
            bp_sh[t][C_] = valid ? (signed char)cur : (signed char)(-1);
            if (valid) cur = bp_sh[t][cur];
        }
    }
    __syncthreads();

    float* po = out + B_ + (size_t)b * L_;
    po[tid] = (float)bp_sh[tid][C_];
}

// ---------------------------------------------------------------------------
extern "C" void kernel_launch(void* const* d_in, const int* in_sizes, int n_in,
                              void* d_out, int out_size){
    const float* feats = (const float*)d_in[0];
    const float* masks = (const float*)d_in[1];
    const float* W     = (const float*)d_in[2];
    const float* bias  = (const float*)d_in[3];
    const float* trans = (const float*)d_in[4];
    float* out = (float*)d_out;

    cudaFuncSetAttribute(emis_kernel, cudaFuncAttributeMaxDynamicSharedMemorySize, SMEM_TOT);
    emis_kernel<<<256, 256, SMEM_TOT>>>(feats, W, bias);
    fwd_kernel<<<B_, 32>>>(masks, trans);
    bp_kernel<<<B_, 512>>>(masks, trans, out);
}